// round 7
// baseline (speedup 1.0000x reference)
#include <cuda_runtime.h>
#include <cstdint>

#define NN   10000
#define FD   128
#define DEG  32
#define OUTC 128
#define XO   120

typedef unsigned long long ull;

__device__ int g_nbr[NN * DEG];
__device__ int g_cnt[NN];

// ---------------- kernel 1: adjacency row -> neighbor list ----------------
__global__ void __launch_bounds__(256) build_nbr(const int* __restrict__ adj) {
    __shared__ int s_cnt;
    const int row = blockIdx.x;
    if (threadIdx.x == 0) s_cnt = 0;
    __syncthreads();
    const int4* rp = reinterpret_cast<const int4*>(adj + (size_t)row * NN);
    for (int c = threadIdx.x; c < NN / 4; c += 256) {
        int4 v = rp[c];
        int base = c * 4;
        if (v.x) { int s = atomicAdd(&s_cnt, 1); if (s < DEG) g_nbr[row * DEG + s] = base + 0; }
        if (v.y) { int s = atomicAdd(&s_cnt, 1); if (s < DEG) g_nbr[row * DEG + s] = base + 1; }
        if (v.z) { int s = atomicAdd(&s_cnt, 1); if (s < DEG) g_nbr[row * DEG + s] = base + 2; }
        if (v.w) { int s = atomicAdd(&s_cnt, 1); if (s < DEG) g_nbr[row * DEG + s] = base + 3; }
    }
    __syncthreads();
    if (threadIdx.x == 0) g_cnt[row] = (s_cnt < DEG) ? s_cnt : DEG;
}

// ---------------- packed f32x2 helpers ----------------
__device__ __forceinline__ ull pack2(float a, float b) {
    ull r; asm("mov.b64 %0, {%1, %2};" : "=l"(r) : "f"(a), "f"(b)); return r;
}
__device__ __forceinline__ void unpack2(ull v, float& a, float& b) {
    asm("mov.b64 {%0, %1}, %2;" : "=f"(a), "=f"(b) : "l"(v));
}
__device__ __forceinline__ ull fma2(ull a, ull b, ull c) {
    ull d; asm("fma.rn.f32x2 %0, %1, %2, %3;" : "=l"(d) : "l"(a), "l"(b), "l"(c)); return d;
}

// ---------------- kernel 2: top-k gather + conv (2 nodes / block) ----------------
// dyn smem: w_s[128*81] | bias_s[128] | sel2[9][128] (float2: .x=nodeA, .y=nodeB)
__global__ void __launch_bounds__(256) lgcl_conv(const float* __restrict__ nf,
                                                const float* __restrict__ cw,
                                                const float* __restrict__ cb,
                                                float* __restrict__ out) {
    extern __shared__ float dsm[];
    float* w_s    = dsm;                       // 10368 floats
    float* bias_s = dsm + 10368;               // 128 floats
    float* selF   = dsm + 10368 + 128;         // 9*128 float2 = 2304 floats

    const int tid = threadIdx.x;

    // stage weights + bias
    for (int i = tid; i < OUTC * 81; i += 256) w_s[i] = cw[i];
    if (tid < OUTC) bias_s[tid] = cb[tid];

    // ---- phase A: per-feature top-8 over neighbors (thread = (node half, column)) ----
    {
        const int h = tid >> 7;                // 0 -> nodeA, 1 -> nodeB
        const int j = tid & 127;               // feature column
        const int node = 2 * blockIdx.x + h;
        const int cnt = g_cnt[node];
        float tk[8];
#pragma unroll
        for (int k = 0; k < 8; k++) tk[k] = -1e30f;
        for (int i = 0; i < cnt; i++) {
            int nb = g_nbr[node * DEG + i];
            float v = nf[(size_t)nb * FD + j];
#pragma unroll
            for (int k = 0; k < 8; k++) { float mx = fmaxf(tk[k], v); v = fminf(tk[k], v); tk[k] = mx; }
        }
        for (int i = cnt; i < 8; i++) {        // zero-padding rows (torch pads before topk)
            float v = 0.0f;
#pragma unroll
            for (int k = 0; k < 8; k++) { float mx = fmaxf(tk[k], v); v = fminf(tk[k], v); tk[k] = mx; }
        }
        selF[(0 * FD + j) * 2 + h] = nf[(size_t)node * FD + j];   // self row, channel 0
#pragma unroll
        for (int k = 0; k < 8; k++)
            selF[((1 + k) * FD + j) * 2 + h] = tk[k];             // k-th largest, channel 1+k
    }
    __syncthreads();

    // ---- phase B: conv1d (channels=9, taps=9, VALID) as packed f32x2 ----
    const int o  = tid & 127;
    const int xb = (tid >> 7) * 60;            // x half: [0,60) or [60,120)
    const size_t nA = (size_t)2 * blockIdx.x;
    float* outA = out + nA * (OUTC * XO) + o * XO;
    float* outB = outA + (size_t)OUTC * XO;
    const float bias = bias_s[o];
    const float* wrow = w_s + o * 81;

    for (int xt = 0; xt < 60; xt += 4) {
        const int x0 = xb + xt;
        ull a0, a1, a2, a3;
        a0 = a1 = a2 = a3 = pack2(bias, bias);
#pragma unroll
        for (int c = 0; c < 9; c++) {
            const ull* srow = reinterpret_cast<const ull*>(selF + (c * FD + x0) * 2);
            ull s[12];
#pragma unroll
            for (int q = 0; q < 12; q++) s[q] = srow[q];
            const float* wc = wrow + c * 9;
#pragma unroll
            for (int t = 0; t < 9; t++) {
                ull ww = pack2(wc[t], wc[t]);
                a0 = fma2(ww, s[t + 0], a0);
                a1 = fma2(ww, s[t + 1], a1);
                a2 = fma2(ww, s[t + 2], a2);
                a3 = fma2(ww, s[t + 3], a3);
            }
        }
        float l0, u0, l1, u1, l2, u2, l3, u3;
        unpack2(a0, l0, u0); unpack2(a1, l1, u1);
        unpack2(a2, l2, u2); unpack2(a3, l3, u3);
        *reinterpret_cast<float4*>(outA + x0) = make_float4(l0, l1, l2, l3);
        *reinterpret_cast<float4*>(outB + x0) = make_float4(u0, u1, u2, u3);
    }
}

extern "C" void kernel_launch(void* const* d_in, const int* in_sizes, int n_in,
                              void* d_out, int out_size) {
    const float* nf  = (const float*)d_in[0];
    const int*   adj = (const int*)d_in[1];
    const float* cw  = (const float*)d_in[2];
    const float* cb  = (const float*)d_in[3];
    float* out = (float*)d_out;
    (void)in_sizes; (void)n_in; (void)out_size;

    const int smem = (10368 + 128 + 2304) * 4;   // 51200 bytes
    cudaFuncSetAttribute(lgcl_conv, cudaFuncAttributeMaxDynamicSharedMemorySize, smem);

    build_nbr<<<NN, 256>>>(adj);
    lgcl_conv<<<NN / 2, 256, smem>>>(nf, cw, cb, out);
}